// round 1
// baseline (speedup 1.0000x reference)
#include <cuda_runtime.h>
#include <math.h>

// Shapes for this problem instance (AdaptiveOutlierLoss): B=32768, C=2048, D=512.
// B and C are derived from in_sizes at launch; D is fixed by the model.
#define DD   512
#define MAXB 32768
#define MAXC 4096

#define BM 128
#define BN 128
#define BK 16
#define SROW 132   // padded SMEM row (floats), keeps float4 alignment

// Scratch (no device allocation allowed -> __device__ globals)
__device__ int   g_min_bits[MAXB];   // ordered-int min of t = max(||x-y||^2,0)/(1-||y||^2)
__device__ float g_x2[MAXB];         // ||x||^2 per z row
__device__ float g_y2[MAXC];         // ||y||^2 per prototype
__device__ float g_inv[MAXC];        // 1/(1-||y||^2)

// ---------------------------------------------------------------------------
// Precompute: squared norms (one warp per row) + init g_min to +inf bits
// ---------------------------------------------------------------------------
__global__ void pre_z_kernel(const float* __restrict__ z, int B) {
    int w    = (blockIdx.x * blockDim.x + threadIdx.x) >> 5;
    int lane = threadIdx.x & 31;
    if (w >= B) return;
    const float* row = z + (size_t)w * DD;
    float s = 0.f;
    #pragma unroll
    for (int k = 0; k < DD / 32; k++) {
        float v = row[lane + 32 * k];
        s = fmaf(v, v, s);
    }
    #pragma unroll
    for (int o = 16; o; o >>= 1) s += __shfl_xor_sync(0xffffffffu, s, o);
    if (lane == 0) {
        g_x2[w]       = s;
        g_min_bits[w] = 0x7F800000;  // +inf
    }
}

__global__ void pre_p_kernel(const float* __restrict__ p, int C) {
    int w    = (blockIdx.x * blockDim.x + threadIdx.x) >> 5;
    int lane = threadIdx.x & 31;
    if (w >= C) return;
    const float* row = p + (size_t)w * DD;
    float s = 0.f;
    #pragma unroll
    for (int k = 0; k < DD / 32; k++) {
        float v = row[lane + 32 * k];
        s = fmaf(v, v, s);
    }
    #pragma unroll
    for (int o = 16; o; o >>= 1) s += __shfl_xor_sync(0xffffffffu, s, o);
    if (lane == 0) {
        g_y2[w]  = s;
        g_inv[w] = 1.0f / (1.0f - s);
    }
}

// ---------------------------------------------------------------------------
// Main kernel: 128x128 tile of dot products over K=512, fused min epilogue.
// t[b][c] = max(x2[b]+y2[c]-2*dot, 0) * inv(1-y2[c]);  g_min[b] = min_c t
// ---------------------------------------------------------------------------
__global__ __launch_bounds__(256, 2)
void min_dist_kernel(const float* __restrict__ Z, const float* __restrict__ P,
                     int B, int C) {
    __shared__ float As[BK][SROW];
    __shared__ float Bs[BK][SROW];
    __shared__ int   sMin[BM];

    const int rowBase = blockIdx.y * BM;
    const int colBase = blockIdx.x * BN;
    const int tid   = threadIdx.x;
    const int ldRow = tid >> 2;      // 0..63
    const int ldC4  = tid & 3;       // which float4 of the 16-float K chunk
    const int ty    = tid >> 4;      // 0..15
    const int tx    = tid & 15;      // 0..15

    const float* zptr = Z + (size_t)rowBase * DD;
    const float* pptr = P + (size_t)colBase * DD;

    float acc[8][8];
    #pragma unroll
    for (int i = 0; i < 8; i++)
        #pragma unroll
        for (int j = 0; j < 8; j++) acc[i][j] = 0.f;

    // prologue: fetch tile 0
    float4 a0 = *(const float4*)(zptr + (size_t)ldRow        * DD + ldC4 * 4);
    float4 a1 = *(const float4*)(zptr + (size_t)(ldRow + 64) * DD + ldC4 * 4);
    float4 b0 = *(const float4*)(pptr + (size_t)ldRow        * DD + ldC4 * 4);
    float4 b1 = *(const float4*)(pptr + (size_t)(ldRow + 64) * DD + ldC4 * 4);

    const int NT = DD / BK;   // 32 K-tiles
    #pragma unroll 1
    for (int t = 0; t < NT; t++) {
        __syncthreads();
        // stage current tile (k-major, transposed)
        As[ldC4 * 4 + 0][ldRow]      = a0.x;
        As[ldC4 * 4 + 1][ldRow]      = a0.y;
        As[ldC4 * 4 + 2][ldRow]      = a0.z;
        As[ldC4 * 4 + 3][ldRow]      = a0.w;
        As[ldC4 * 4 + 0][ldRow + 64] = a1.x;
        As[ldC4 * 4 + 1][ldRow + 64] = a1.y;
        As[ldC4 * 4 + 2][ldRow + 64] = a1.z;
        As[ldC4 * 4 + 3][ldRow + 64] = a1.w;
        Bs[ldC4 * 4 + 0][ldRow]      = b0.x;
        Bs[ldC4 * 4 + 1][ldRow]      = b0.y;
        Bs[ldC4 * 4 + 2][ldRow]      = b0.z;
        Bs[ldC4 * 4 + 3][ldRow]      = b0.w;
        Bs[ldC4 * 4 + 0][ldRow + 64] = b1.x;
        Bs[ldC4 * 4 + 1][ldRow + 64] = b1.y;
        Bs[ldC4 * 4 + 2][ldRow + 64] = b1.z;
        Bs[ldC4 * 4 + 3][ldRow + 64] = b1.w;
        __syncthreads();

        // prefetch next tile (latency hidden under the 1024-FFMA compute below)
        if (t + 1 < NT) {
            int k0 = (t + 1) * BK;
            a0 = *(const float4*)(zptr + (size_t)ldRow        * DD + k0 + ldC4 * 4);
            a1 = *(const float4*)(zptr + (size_t)(ldRow + 64) * DD + k0 + ldC4 * 4);
            b0 = *(const float4*)(pptr + (size_t)ldRow        * DD + k0 + ldC4 * 4);
            b1 = *(const float4*)(pptr + (size_t)(ldRow + 64) * DD + k0 + ldC4 * 4);
        }

        #pragma unroll
        for (int k = 0; k < BK; k++) {
            float4 av0 = *(const float4*)&As[k][ty * 8];
            float4 av1 = *(const float4*)&As[k][ty * 8 + 4];
            float4 bv0 = *(const float4*)&Bs[k][tx * 8];
            float4 bv1 = *(const float4*)&Bs[k][tx * 8 + 4];
            float a[8] = {av0.x, av0.y, av0.z, av0.w, av1.x, av1.y, av1.z, av1.w};
            float b[8] = {bv0.x, bv0.y, bv0.z, bv0.w, bv1.x, bv1.y, bv1.z, bv1.w};
            #pragma unroll
            for (int i = 0; i < 8; i++)
                #pragma unroll
                for (int j = 0; j < 8; j++)
                    acc[i][j] = fmaf(a[i], b[j], acc[i][j]);
        }
    }

    // epilogue: fused per-row min of t = max(x2+y2-2*dot,0)/(1-y2)
    float x2r[8], y2v[8], iv[8];
    #pragma unroll
    for (int i = 0; i < 8; i++) x2r[i] = g_x2[rowBase + ty * 8 + i];
    #pragma unroll
    for (int j = 0; j < 8; j++) {
        y2v[j] = g_y2[colBase + tx * 8 + j];
        iv[j]  = g_inv[colBase + tx * 8 + j];
    }

    if (tid < BM) sMin[tid] = 0x7F800000;
    __syncthreads();

    #pragma unroll
    for (int i = 0; i < 8; i++) {
        float m = __int_as_float(0x7F800000);
        #pragma unroll
        for (int j = 0; j < 8; j++) {
            float sq = fmaxf(x2r[i] + y2v[j] - 2.0f * acc[i][j], 0.0f);
            m = fminf(m, sq * iv[j]);
        }
        // all t >= 0 -> int-bit compare preserves float order
        atomicMin(&sMin[ty * 8 + i], __float_as_int(m));
    }
    __syncthreads();
    if (tid < BM) atomicMin(&g_min_bits[rowBase + tid], sMin[tid]);
}

// ---------------------------------------------------------------------------
// Finalize: arg = 1 + 2*t/(1-x2); d = acosh(max(arg, 1+eps));
// loss = mean(relu(margin - d)). Single block -> deterministic, no atomics.
// ---------------------------------------------------------------------------
__global__ void finalize_kernel(const float* __restrict__ margin_p,
                                float* __restrict__ out, int B) {
    __shared__ float sred[32];
    const int tid = threadIdx.x;
    const float margin = *margin_p;
    float acc = 0.f;
    for (int b = tid; b < B; b += blockDim.x) {
        float t   = __int_as_float(g_min_bits[b]);
        float x2  = g_x2[b];
        float arg = 1.0f + 2.0f * t / (1.0f - x2);
        arg = fmaxf(arg, 1.0f + 1e-7f);
        float d = acoshf(arg);
        acc += fmaxf(margin - d, 0.0f);
    }
    #pragma unroll
    for (int o = 16; o; o >>= 1) acc += __shfl_xor_sync(0xffffffffu, acc, o);
    if ((tid & 31) == 0) sred[tid >> 5] = acc;
    __syncthreads();
    if (tid < 32) {
        float v = (tid < (int)(blockDim.x >> 5)) ? sred[tid] : 0.f;
        #pragma unroll
        for (int o = 16; o; o >>= 1) v += __shfl_xor_sync(0xffffffffu, v, o);
        if (tid == 0) out[0] = v / (float)B;
    }
}

// ---------------------------------------------------------------------------
extern "C" void kernel_launch(void* const* d_in, const int* in_sizes, int n_in,
                              void* d_out, int out_size) {
    const float* z      = (const float*)d_in[0];
    const float* protos = (const float*)d_in[1];
    const float* margin = (const float*)d_in[2];
    float* out = (float*)d_out;

    const int B = in_sizes[0] / DD;   // 32768
    const int C = in_sizes[1] / DD;   // 2048

    {
        int warps  = B;
        int blocks = (warps * 32 + 255) / 256;
        pre_z_kernel<<<blocks, 256>>>(z, B);
    }
    {
        int warps  = C;
        int blocks = (warps * 32 + 255) / 256;
        pre_p_kernel<<<blocks, 256>>>(protos, C);
    }
    {
        dim3 grid(C / BN, B / BM);    // (16, 256)
        min_dist_kernel<<<grid, 256>>>(z, protos, B, C);
    }
    finalize_kernel<<<1, 1024>>>(margin, out, B);
}

// round 4
// speedup vs baseline: 4.8245x; 4.8245x over previous
#include <cuda_runtime.h>
#include <cuda_bf16.h>
#include <cstdint>
#include <math.h>

// ============================================================================
// AdaptiveOutlierLoss: mean(relu(margin - min_c d_poincare(z_b, p_c)))
// B=32768, C=2048, D=512. arccosh monotone + (1-|x|^2) row-constant =>
// argmin_c d == argmin_c (x2 + y2 - 2 dot) / (1 - y2).
// bf16 warp-MMA (m16n8k16) GEMM with fused min epilogue. No tcgen05 (the
// bench's virtual arch is compute_103, which rejects sm_103a-only PTX).
// ============================================================================

#define DDIM 512
#define MAXB 32768
#define MAXC 2048

// ---------------- device scratch ----------------
__device__ __align__(128) unsigned char g_zt[(size_t)MAXB * DDIM * 2];  // bf16 z, row-major
__device__ __align__(128) unsigned char g_pt[(size_t)MAXC * DDIM * 2];  // bf16 protos
__device__ float  g_x2[MAXB];
__device__ float2 g_pc[MAXC];        // (y2, 1/(1-y2)) per prototype
__device__ float  g_tmin[MAXB];
__device__ float  g_partial[MAXB / 128];

// ---------------- SMEM map (main kernel) ----------------
// A: 16 k-chunks x [128 rows x 80B]   (32 k bf16 = 64B data + 16B pad)
// B: 4 stages   x [128 rows x 80B]
#define SM_A      0
#define SM_B      163840
#define SM_MIN    204800
#define SMEM_MAIN 205312

// ---------------- asm helpers ----------------
__device__ __forceinline__ uint32_t smem_u32(const void* p) {
    uint32_t a;
    asm("{ .reg .u64 t; cvta.to.shared.u64 t, %1; cvt.u32.u64 %0, t; }" : "=r"(a) : "l"(p));
    return a;
}
__device__ __forceinline__ void cp16(uint32_t dst, const void* src) {
    asm volatile("cp.async.cg.shared.global [%0], [%1], 16;" :: "r"(dst), "l"(src) : "memory");
}
__device__ __forceinline__ void cp_commit() {
    asm volatile("cp.async.commit_group;" ::: "memory");
}
template <int N>
__device__ __forceinline__ void cp_wait() {
    asm volatile("cp.async.wait_group %0;" :: "n"(N) : "memory");
}
#define LDSM4(r, addr)                                                          \
    asm volatile("ldmatrix.sync.aligned.m8n8.x4.shared.b16 {%0,%1,%2,%3}, [%4];" \
                 : "=r"((r)[0]), "=r"((r)[1]), "=r"((r)[2]), "=r"((r)[3])       \
                 : "r"(addr))
__device__ __forceinline__ void mma16816(float* d, const uint32_t* a,
                                         uint32_t b0, uint32_t b1) {
    asm volatile(
        "mma.sync.aligned.m16n8k16.row.col.f32.bf16.bf16.f32 "
        "{%0,%1,%2,%3}, {%4,%5,%6,%7}, {%8,%9}, {%0,%1,%2,%3};"
        : "+f"(d[0]), "+f"(d[1]), "+f"(d[2]), "+f"(d[3])
        : "r"(a[0]), "r"(a[1]), "r"(a[2]), "r"(a[3]), "r"(b0), "r"(b1));
}

__device__ __forceinline__ unsigned long long pack4_bf16(float4 v) {
    unsigned long long a = __bfloat16_as_ushort(__float2bfloat16(v.x));
    unsigned long long b = __bfloat16_as_ushort(__float2bfloat16(v.y));
    unsigned long long c = __bfloat16_as_ushort(__float2bfloat16(v.z));
    unsigned long long d = __bfloat16_as_ushort(__float2bfloat16(v.w));
    return a | (b << 16) | (c << 32) | (d << 48);
}

// ============================================================================
// Conversion: fp32 -> bf16 row-major, fused squared-norm (one warp per row).
// ============================================================================
__global__ void conv_z_kernel(const float* __restrict__ z, int B) {
    int w    = (blockIdx.x * blockDim.x + threadIdx.x) >> 5;
    int lane = threadIdx.x & 31;
    if (w >= B) return;
    const float* row = z + (size_t)w * DDIM;
    float s = 0.f;
    #pragma unroll
    for (int i = 0; i < 4; i++) {
        int f = i * 32 + lane;                 // float4 index
        float4 v = *(const float4*)(row + f * 4);
        s = fmaf(v.x, v.x, fmaf(v.y, v.y, fmaf(v.z, v.z, fmaf(v.w, v.w, s))));
        *(unsigned long long*)(g_zt + (size_t)w * 1024 + f * 8) = pack4_bf16(v);
    }
    #pragma unroll
    for (int o = 16; o; o >>= 1) s += __shfl_xor_sync(0xffffffffu, s, o);
    if (lane == 0) g_x2[w] = s;
}

__global__ void conv_p_kernel(const float* __restrict__ p, int C) {
    int w    = (blockIdx.x * blockDim.x + threadIdx.x) >> 5;
    int lane = threadIdx.x & 31;
    if (w >= C) return;
    const float* row = p + (size_t)w * DDIM;
    float s = 0.f;
    #pragma unroll
    for (int i = 0; i < 4; i++) {
        int f = i * 32 + lane;
        float4 v = *(const float4*)(row + f * 4);
        s = fmaf(v.x, v.x, fmaf(v.y, v.y, fmaf(v.z, v.z, fmaf(v.w, v.w, s))));
        *(unsigned long long*)(g_pt + (size_t)w * 1024 + f * 8) = pack4_bf16(v);
    }
    #pragma unroll
    for (int o = 16; o; o >>= 1) s += __shfl_xor_sync(0xffffffffu, s, o);
    if (lane == 0) g_pc[w] = make_float2(s, 1.0f / (1.0f - s));
}

// ============================================================================
// Main kernel: 1 CTA per 128 z-rows. A resident in SMEM (pitch 80 => ldmatrix
// conflict-free). B = 128 protos x 32 k per stage, 4-stage cp.async pipeline.
// 8 warps: warp tile 64(m) x 32(n), m16n8k16 bf16 -> fp32.
// ============================================================================
__global__ void __launch_bounds__(256, 1)
min_dist_mma_kernel(int C) {
    extern __shared__ char smem[];
    const uint32_t sb   = smem_u32(smem);
    const int tid  = threadIdx.x;
    const int lane = tid & 31;
    const int wid  = tid >> 5;
    const int wm   = wid & 1;     // m block of 64
    const int wn   = wid >> 1;    // n block of 32
    const int mb   = blockIdx.x;
    const int NB   = C >> 7;
    const int NQ   = NB * 16;     // total (nb,kc) stages

    int* sMin = (int*)(smem + SM_MIN);
    if (tid < 128) sMin[tid] = 0x7F800000;

    // ---- prologue: A (whole 128x512 slice) + first 3 B stages ----
    {
        const char* abase = (const char*)g_zt + (size_t)mb * 131072;
        #pragma unroll 4
        for (int t = 0; t < 32; t++) {
            int i  = tid + t * 256;        // 8192 16B chunks
            int r  = i >> 6;
            int j  = i & 63;               // 16B chunk within row
            cp16(sb + SM_A + (j >> 2) * 10240 + r * 80 + (j & 3) * 16,
                 abase + r * 1024 + j * 16);
        }
    }
    auto load_B = [&](int s, int q) {
        int nb = q >> 4, kc = q & 15;
        const char* bbase = (const char*)g_pt + (size_t)nb * 131072 + kc * 64;
        #pragma unroll
        for (int t = 0; t < 2; t++) {
            int i = tid + t * 256;         // 512 chunks
            int r = i >> 2, cj = i & 3;
            cp16(sb + SM_B + s * 10240 + r * 80 + cj * 16,
                 bbase + r * 1024 + cj * 16);
        }
    };
    load_B(0, 0); cp_commit();             // group0 = A + B0
    load_B(1, 1); cp_commit();
    load_B(2, 2); cp_commit();

    // ---- per-thread constants ----
    const int g = lane >> 2;
    float x2r[8];
    #pragma unroll
    for (int mt = 0; mt < 4; mt++) {
        int r0 = mb * 128 + wm * 64 + mt * 16 + g;
        x2r[mt * 2]     = g_x2[r0];
        x2r[mt * 2 + 1] = g_x2[r0 + 8];
    }
    float rm[8];
    #pragma unroll
    for (int i = 0; i < 8; i++) rm[i] = __int_as_float(0x7F800000);

    float acc[4][4][4];
    #pragma unroll
    for (int mt = 0; mt < 4; mt++)
        #pragma unroll
        for (int nt = 0; nt < 4; nt++)
            #pragma unroll
            for (int k = 0; k < 4; k++) acc[mt][nt][k] = 0.f;

    const uint32_t aoff = sb + SM_A + (wm * 64 + (lane & 15)) * 80 + (lane >> 4) * 16;
    const uint32_t boff = sb + SM_B + (wn * 32 + (lane & 15)) * 80 + (lane >> 4) * 16;

    #pragma unroll 1
    for (int q = 0; q < NQ; q++) {
        const int s  = q & 3;
        const int kc = q & 15;
        const int nb = q >> 4;
        const int rem = NQ - 1 - q;
        if (rem >= 2)      cp_wait<2>();
        else if (rem == 1) cp_wait<1>();
        else               cp_wait<0>();
        __syncthreads();
        if (q + 3 < NQ) { load_B((q + 3) & 3, q + 3); cp_commit(); }

        // load fragments
        uint32_t afr[4][2][4];
        uint32_t bfr[2][2][4];
        #pragma unroll
        for (int mt = 0; mt < 4; mt++)
            #pragma unroll
            for (int h = 0; h < 2; h++)
                LDSM4(afr[mt][h], aoff + kc * 10240 + mt * 1280 + h * 32);
        #pragma unroll
        for (int p = 0; p < 2; p++)
            #pragma unroll
            for (int h = 0; h < 2; h++)
                LDSM4(bfr[p][h], boff + s * 10240 + p * 1280 + h * 32);

        #pragma unroll
        for (int h = 0; h < 2; h++)
            #pragma unroll
            for (int mt = 0; mt < 4; mt++)
                #pragma unroll
                for (int nt = 0; nt < 4; nt++) {
                    int p = nt >> 1, sd = nt & 1;
                    mma16816(acc[mt][nt], afr[mt][h],
                             bfr[p][h][sd], bfr[p][h][sd + 2]);
                }

        if (kc == 15) {
            // epilogue for this 128-proto block: fold min, reset acc
            const int colbase = nb * 128 + wn * 32 + (lane & 3) * 2;
            #pragma unroll
            for (int nt = 0; nt < 4; nt++) {
                float2 pa = __ldg(&g_pc[colbase + nt * 8]);
                float2 pb = __ldg(&g_pc[colbase + nt * 8 + 1]);
                #pragma unroll
                for (int mt = 0; mt < 4; mt++) {
                    float v00 = (x2r[mt*2]   + pa.x - 2.0f * acc[mt][nt][0]) * pa.y;
                    float v01 = (x2r[mt*2]   + pb.x - 2.0f * acc[mt][nt][1]) * pb.y;
                    float v10 = (x2r[mt*2+1] + pa.x - 2.0f * acc[mt][nt][2]) * pa.y;
                    float v11 = (x2r[mt*2+1] + pb.x - 2.0f * acc[mt][nt][3]) * pb.y;
                    rm[mt*2]   = fminf(rm[mt*2],   fminf(v00, v01));
                    rm[mt*2+1] = fminf(rm[mt*2+1], fminf(v10, v11));
                    acc[mt][nt][0] = 0.f; acc[mt][nt][1] = 0.f;
                    acc[mt][nt][2] = 0.f; acc[mt][nt][3] = 0.f;
                }
            }
        }
    }

    // ---- cross-warp min + writeback (values >= 0 => int-bit order) ----
    __syncthreads();
    #pragma unroll
    for (int mt = 0; mt < 4; mt++) {
        atomicMin(&sMin[wm * 64 + mt * 16 + g],     __float_as_int(rm[mt*2]));
        atomicMin(&sMin[wm * 64 + mt * 16 + g + 8], __float_as_int(rm[mt*2+1]));
    }
    __syncthreads();
    if (tid < 128) g_tmin[mb * 128 + tid] = __int_as_float(sMin[tid]);
}

// ============================================================================
// Finalize: deterministic two-stage reduction.
// ============================================================================
__global__ void fin1_kernel(const float* __restrict__ margin_p) {
    __shared__ float red[4];
    const int r = blockIdx.x * 128 + threadIdx.x;
    const float margin = *margin_p;
    float t   = g_tmin[r];
    float x2  = g_x2[r];
    float arg = fmaxf(1.0f + 2.0f * t / (1.0f - x2), 1.0f + 1e-7f);
    float v   = fmaxf(margin - acoshf(arg), 0.0f);
    #pragma unroll
    for (int o = 16; o; o >>= 1) v += __shfl_xor_sync(0xffffffffu, v, o);
    if ((threadIdx.x & 31) == 0) red[threadIdx.x >> 5] = v;
    __syncthreads();
    if (threadIdx.x == 0)
        g_partial[blockIdx.x] = red[0] + red[1] + red[2] + red[3];
}

__global__ void fin2_kernel(float* __restrict__ out, int nblk, int B) {
    __shared__ float red[32];
    float s = 0.f;
    for (int i = threadIdx.x; i < nblk; i += blockDim.x) s += g_partial[i];
    #pragma unroll
    for (int o = 16; o; o >>= 1) s += __shfl_xor_sync(0xffffffffu, s, o);
    if ((threadIdx.x & 31) == 0) red[threadIdx.x >> 5] = s;
    __syncthreads();
    if (threadIdx.x < 32) {
        float v = (threadIdx.x < (blockDim.x >> 5)) ? red[threadIdx.x] : 0.f;
        #pragma unroll
        for (int o = 16; o; o >>= 1) v += __shfl_xor_sync(0xffffffffu, v, o);
        if (threadIdx.x == 0) out[0] = v / (float)B;
    }
}

// ============================================================================
extern "C" void kernel_launch(void* const* d_in, const int* in_sizes, int n_in,
                              void* d_out, int out_size) {
    const float* z      = (const float*)d_in[0];
    const float* protos = (const float*)d_in[1];
    const float* margin = (const float*)d_in[2];
    float* out = (float*)d_out;

    const int B = in_sizes[0] / DDIM;   // 32768
    const int C = in_sizes[1] / DDIM;   // 2048

    cudaFuncSetAttribute(min_dist_mma_kernel,
                         cudaFuncAttributeMaxDynamicSharedMemorySize, SMEM_MAIN);

    conv_z_kernel<<<(B + 7) / 8, 256>>>(z, B);
    conv_p_kernel<<<(C + 7) / 8, 256>>>(protos, C);
    min_dist_mma_kernel<<<B / 128, 256, SMEM_MAIN>>>(C);
    fin1_kernel<<<B / 128, 128>>>(margin);
    fin2_kernel<<<1, 256>>>(out, B / 128, B);
}

// round 5
// speedup vs baseline: 5.7704x; 1.1960x over previous
#include <cuda_runtime.h>
#include <cuda_fp8.h>
#include <cstdint>
#include <math.h>

// ============================================================================
// AdaptiveOutlierLoss: mean(relu(margin - min_c d_poincare(z_b, p_c)))
// B=32768, C=2048, D=512. arccosh monotone + (1-|x|^2) row-constant =>
// argmin_c d == argmin_c (x2 + y2 - 2 dot) / (1 - y2).
// FP8 e4m3 warp-MMA (m16n8k32, 2x MACs/instr vs bf16 16816) with fused min
// epilogue. Inputs pre-scaled by 16 into e4m3's normal range; norms stay fp32.
// ============================================================================

#define DDIM 512
#define MAXB 32768
#define MAXC 2048

// ---------------- device scratch ----------------
__device__ __align__(128) unsigned char g_zt[(size_t)MAXB * DDIM];  // fp8 z (x16)
__device__ __align__(128) unsigned char g_pt[(size_t)MAXC * DDIM];  // fp8 protos (x16)
__device__ float  g_x2[MAXB];
__device__ float2 g_pc[MAXC];        // (y2, 1/(1-y2)) per prototype
__device__ float  g_tmin[MAXB];
__device__ float  g_partial[MAXB / 128];

// ---------------- SMEM map ----------------
// A: 8 k-chunks x [128 rows x 80B]  (64 fp8 k = 64B data + 16B pad)
// B: 4 stages  x [128 rows x 80B]
#define SM_A      0
#define SM_B      81920
#define SM_MIN    122880
#define SMEM_MAIN 123392

// ---------------- asm helpers ----------------
__device__ __forceinline__ uint32_t smem_u32(const void* p) {
    uint32_t a;
    asm("{ .reg .u64 t; cvta.to.shared.u64 t, %1; cvt.u32.u64 %0, t; }" : "=r"(a) : "l"(p));
    return a;
}
__device__ __forceinline__ void cp16(uint32_t dst, const void* src) {
    asm volatile("cp.async.cg.shared.global [%0], [%1], 16;" :: "r"(dst), "l"(src) : "memory");
}
__device__ __forceinline__ void cp_commit() {
    asm volatile("cp.async.commit_group;" ::: "memory");
}
template <int N>
__device__ __forceinline__ void cp_wait() {
    asm volatile("cp.async.wait_group %0;" :: "n"(N) : "memory");
}
#define LDSM4(r, addr)                                                           \
    asm volatile("ldmatrix.sync.aligned.m8n8.x4.shared.b16 {%0,%1,%2,%3}, [%4];" \
                 : "=r"((r)[0]), "=r"((r)[1]), "=r"((r)[2]), "=r"((r)[3])        \
                 : "r"(addr))
__device__ __forceinline__ void mma_fp8(float* d, const uint32_t* a,
                                        uint32_t b0, uint32_t b1) {
    asm volatile(
        "mma.sync.aligned.m16n8k32.row.col.f32.e4m3.e4m3.f32 "
        "{%0,%1,%2,%3}, {%4,%5,%6,%7}, {%8,%9}, {%0,%1,%2,%3};"
        : "+f"(d[0]), "+f"(d[1]), "+f"(d[2]), "+f"(d[3])
        : "r"(a[0]), "r"(a[1]), "r"(a[2]), "r"(a[3]), "r"(b0), "r"(b1));
}

// fp32x4 -> 4 packed e4m3 bytes, pre-scaled by 16
__device__ __forceinline__ uint32_t pack4_fp8(float4 v) {
    __nv_fp8x2_storage_t lo =
        __nv_cvt_float2_to_fp8x2(make_float2(v.x * 16.0f, v.y * 16.0f), __NV_SATFINITE, __NV_E4M3);
    __nv_fp8x2_storage_t hi =
        __nv_cvt_float2_to_fp8x2(make_float2(v.z * 16.0f, v.w * 16.0f), __NV_SATFINITE, __NV_E4M3);
    return (uint32_t)lo | ((uint32_t)hi << 16);
}

// ============================================================================
// Conversion: fp32 -> fp8 row-major (scaled x16), fused fp32 squared-norm.
// One warp per row.
// ============================================================================
__global__ void conv_z_kernel(const float* __restrict__ z, int B) {
    int w    = (blockIdx.x * blockDim.x + threadIdx.x) >> 5;
    int lane = threadIdx.x & 31;
    if (w >= B) return;
    const float* row = z + (size_t)w * DDIM;
    float s = 0.f;
    #pragma unroll
    for (int i = 0; i < 4; i++) {
        int f = i * 32 + lane;                 // float4 index
        float4 v = *(const float4*)(row + f * 4);
        s = fmaf(v.x, v.x, fmaf(v.y, v.y, fmaf(v.z, v.z, fmaf(v.w, v.w, s))));
        *(uint32_t*)(g_zt + (size_t)w * DDIM + f * 4) = pack4_fp8(v);
    }
    #pragma unroll
    for (int o = 16; o; o >>= 1) s += __shfl_xor_sync(0xffffffffu, s, o);
    if (lane == 0) g_x2[w] = s;
}

__global__ void conv_p_kernel(const float* __restrict__ p, int C) {
    int w    = (blockIdx.x * blockDim.x + threadIdx.x) >> 5;
    int lane = threadIdx.x & 31;
    if (w >= C) return;
    const float* row = p + (size_t)w * DDIM;
    float s = 0.f;
    #pragma unroll
    for (int i = 0; i < 4; i++) {
        int f = i * 32 + lane;
        float4 v = *(const float4*)(row + f * 4);
        s = fmaf(v.x, v.x, fmaf(v.y, v.y, fmaf(v.z, v.z, fmaf(v.w, v.w, s))));
        *(uint32_t*)(g_pt + (size_t)w * DDIM + f * 4) = pack4_fp8(v);
    }
    #pragma unroll
    for (int o = 16; o; o >>= 1) s += __shfl_xor_sync(0xffffffffu, s, o);
    if (lane == 0) g_pc[w] = make_float2(s, 1.0f / (1.0f - s));
}

// ============================================================================
// Main kernel: 1 CTA per 128 z-rows. A (128x512 fp8) resident in SMEM at
// pitch 80 (5x16B: gcd(5,8)=1 -> ldmatrix conflict-free). B = 128 protos x
// 64 k per stage, 4-stage cp.async pipeline. 8 warps, warp tile 64(m)x32(n),
// m16n8k32 e4m3 -> fp32; per-N-block min folded in registers.
// ============================================================================
__global__ void __launch_bounds__(256, 1)
min_dist_mma_kernel(int C) {
    extern __shared__ char smem[];
    const uint32_t sb   = smem_u32(smem);
    const int tid  = threadIdx.x;
    const int lane = tid & 31;
    const int wid  = tid >> 5;
    const int wm   = wid & 1;     // m block of 64
    const int wn   = wid >> 1;    // n block of 32
    const int mb   = blockIdx.x;
    const int NB   = C >> 7;      // 128-proto blocks
    const int NQ   = NB * 8;      // stages (64 k each)

    int* sMin = (int*)(smem + SM_MIN);
    if (tid < 128) sMin[tid] = 0x7F800000;

    // ---- prologue: A (whole 128x512B slice) + first 3 B stages ----
    {
        const char* abase = (const char*)g_zt + (size_t)mb * 65536;
        #pragma unroll 4
        for (int t = 0; t < 16; t++) {
            int i = tid + t * 256;          // 4096 16B chunks
            int r = i >> 5;                 // row 0..127 (32 chunks per row)
            int j = i & 31;                 // chunk within row: kchunk = j>>2
            cp16(sb + SM_A + (j >> 2) * 10240 + r * 80 + (j & 3) * 16,
                 abase + r * 512 + j * 16);
        }
    }
    auto load_B = [&](int s, int q) {
        int nb = q >> 3, kc = q & 7;
        const char* bbase = (const char*)g_pt + (size_t)nb * 65536 + kc * 64;
        #pragma unroll
        for (int t = 0; t < 2; t++) {
            int i = tid + t * 256;          // 512 chunks (128 rows x 4)
            int r = i >> 2, slot = i & 3;
            cp16(sb + SM_B + s * 10240 + r * 80 + slot * 16,
                 bbase + r * 512 + slot * 16);
        }
    };
    load_B(0, 0); cp_commit();              // group0 = A + B0
    load_B(1, 1); cp_commit();
    load_B(2, 2); cp_commit();

    // ---- per-thread constants ----
    const int g = lane >> 2;
    float x2r[8];
    #pragma unroll
    for (int mt = 0; mt < 4; mt++) {
        int r0 = mb * 128 + wm * 64 + mt * 16 + g;
        x2r[mt * 2]     = g_x2[r0];
        x2r[mt * 2 + 1] = g_x2[r0 + 8];
    }
    float rm[8];
    #pragma unroll
    for (int i = 0; i < 8; i++) rm[i] = __int_as_float(0x7F800000);

    float acc[4][4][4];
    #pragma unroll
    for (int mt = 0; mt < 4; mt++)
        #pragma unroll
        for (int nt = 0; nt < 4; nt++)
            #pragma unroll
            for (int k = 0; k < 4; k++) acc[mt][nt][k] = 0.f;

    const uint32_t aoff = sb + SM_A + (wm * 64 + (lane & 15)) * 80 + (lane >> 4) * 16;
    const uint32_t boff = sb + SM_B + (wn * 32 + (lane & 15)) * 80 + (lane >> 4) * 16;

    #pragma unroll 1
    for (int q = 0; q < NQ; q++) {
        const int s  = q & 3;
        const int kc = q & 7;
        const int nb = q >> 3;
        const int rem = NQ - 1 - q;
        if (rem >= 2)      cp_wait<2>();
        else if (rem == 1) cp_wait<1>();
        else               cp_wait<0>();
        __syncthreads();
        if (q + 3 < NQ) { load_B((q + 3) & 3, q + 3); cp_commit(); }

        // fragments: each ldsm x4 = 16 rows x 32 fp8 k (one full k32 fragment)
        uint32_t afr[4][2][4];
        uint32_t bfr[2][2][4];
        #pragma unroll
        for (int mt = 0; mt < 4; mt++)
            #pragma unroll
            for (int ks = 0; ks < 2; ks++)
                LDSM4(afr[mt][ks], aoff + kc * 10240 + mt * 1280 + ks * 32);
        #pragma unroll
        for (int p = 0; p < 2; p++)
            #pragma unroll
            for (int ks = 0; ks < 2; ks++)
                LDSM4(bfr[p][ks], boff + s * 10240 + p * 1280 + ks * 32);

        #pragma unroll
        for (int ks = 0; ks < 2; ks++)
            #pragma unroll
            for (int mt = 0; mt < 4; mt++)
                #pragma unroll
                for (int nt = 0; nt < 4; nt++) {
                    int p = nt >> 1, sd = nt & 1;
                    mma_fp8(acc[mt][nt], afr[mt][ks],
                            bfr[p][ks][sd], bfr[p][ks][sd + 2]);
                }

        if (kc == 7) {
            // epilogue for this 128-proto block: acc holds 256*dot
            const int colbase = nb * 128 + wn * 32 + (lane & 3) * 2;
            #pragma unroll
            for (int nt = 0; nt < 4; nt++) {
                float2 pa = __ldg(&g_pc[colbase + nt * 8]);
                float2 pb = __ldg(&g_pc[colbase + nt * 8 + 1]);
                #pragma unroll
                for (int mt = 0; mt < 4; mt++) {
                    float v00 = fmaf(-0.0078125f, acc[mt][nt][0], x2r[mt*2]   + pa.x) * pa.y;
                    float v01 = fmaf(-0.0078125f, acc[mt][nt][1], x2r[mt*2]   + pb.x) * pb.y;
                    float v10 = fmaf(-0.0078125f, acc[mt][nt][2], x2r[mt*2+1] + pa.x) * pa.y;
                    float v11 = fmaf(-0.0078125f, acc[mt][nt][3], x2r[mt*2+1] + pb.x) * pb.y;
                    rm[mt*2]   = fminf(rm[mt*2],   fminf(v00, v01));
                    rm[mt*2+1] = fminf(rm[mt*2+1], fminf(v10, v11));
                    acc[mt][nt][0] = 0.f; acc[mt][nt][1] = 0.f;
                    acc[mt][nt][2] = 0.f; acc[mt][nt][3] = 0.f;
                }
            }
        }
    }

    // ---- cross-warp min + writeback (values' float order == int order here) ----
    __syncthreads();
    #pragma unroll
    for (int mt = 0; mt < 4; mt++) {
        atomicMin(&sMin[wm * 64 + mt * 16 + g],     __float_as_int(rm[mt*2]));
        atomicMin(&sMin[wm * 64 + mt * 16 + g + 8], __float_as_int(rm[mt*2+1]));
    }
    __syncthreads();
    if (tid < 128) g_tmin[mb * 128 + tid] = __int_as_float(sMin[tid]);
}

// ============================================================================
// Finalize: deterministic two-stage reduction.
// ============================================================================
__global__ void fin1_kernel(const float* __restrict__ margin_p) {
    __shared__ float red[4];
    const int r = blockIdx.x * 128 + threadIdx.x;
    const float margin = *margin_p;
    float t   = g_tmin[r];
    float x2  = g_x2[r];
    float arg = fmaxf(1.0f + 2.0f * t / (1.0f - x2), 1.0f + 1e-7f);
    float v   = fmaxf(margin - acoshf(arg), 0.0f);
    #pragma unroll
    for (int o = 16; o; o >>= 1) v += __shfl_xor_sync(0xffffffffu, v, o);
    if ((threadIdx.x & 31) == 0) red[threadIdx.x >> 5] = v;
    __syncthreads();
    if (threadIdx.x == 0)
        g_partial[blockIdx.x] = red[0] + red[1] + red[2] + red[3];
}

__global__ void fin2_kernel(float* __restrict__ out, int nblk, int B) {
    __shared__ float red[32];
    float s = 0.f;
    for (int i = threadIdx.x; i < nblk; i += blockDim.x) s += g_partial[i];
    #pragma unroll
    for (int o = 16; o; o >>= 1) s += __shfl_xor_sync(0xffffffffu, s, o);
    if ((threadIdx.x & 31) == 0) red[threadIdx.x >> 5] = s;
    __syncthreads();
    if (threadIdx.x < 32) {
        float v = (threadIdx.x < (blockDim.x >> 5)) ? red[threadIdx.x] : 0.f;
        #pragma unroll
        for (int o = 16; o; o >>= 1) v += __shfl_xor_sync(0xffffffffu, v, o);
        if (threadIdx.x == 0) out[0] = v / (float)B;
    }
}

// ============================================================================
extern "C" void kernel_launch(void* const* d_in, const int* in_sizes, int n_in,
                              void* d_out, int out_size) {
    const float* z      = (const float*)d_in[0];
    const float* protos = (const float*)d_in[1];
    const float* margin = (const float*)d_in[2];
    float* out = (float*)d_out;

    const int B = in_sizes[0] / DDIM;   // 32768
    const int C = in_sizes[1] / DDIM;   // 2048

    cudaFuncSetAttribute(min_dist_mma_kernel,
                         cudaFuncAttributeMaxDynamicSharedMemorySize, SMEM_MAIN);

    conv_z_kernel<<<(B + 7) / 8, 256>>>(z, B);
    conv_p_kernel<<<(C + 7) / 8, 256>>>(protos, C);
    min_dist_mma_kernel<<<B / 128, 256, SMEM_MAIN>>>(C);
    fin1_kernel<<<B / 128, 128>>>(margin);
    fin2_kernel<<<1, 256>>>(out, B / 128, B);
}